// round 2
// baseline (speedup 1.0000x reference)
#include <cuda_runtime.h>

#define BB   4
#define NN   512
#define FD   256
#define AD   256
#define DP   64
#define PD   128
#define ROWS (BB*NN)          /* 2048 */
#define NPAIR (BB*NN*NN)      /* 1048576 */
#define EPSF 1e-3f
#define SCAL 0.0625f          /* 1/sqrt(256) */

#define BIAS_BLOCKS 8192      /* 1048576 rows / 128 rows per block */
#define T_TILES     128       /* (2048/64) * (256/64) */

// ---------------- scratch (device globals; no allocation allowed) ----------
__device__ float d_Fn[ROWS*FD];
__device__ float d_M[FD*FD];         // Wq @ Wk^T
__device__ float d_T[ROWS*FD];       // Fn @ M
__device__ float d_vsum[ROWS];
__device__ float d_gw[DP];
__device__ float d_sgw;
__device__ float d_bconst;
__device__ float d_wvsum[FD];
__device__ float d_bias[NPAIR];
__device__ float d_S[NPAIR];

// ---------------- helpers ---------------------------------------------------
__device__ __forceinline__ float block_sum256(float v, float* red) {
    int t = threadIdx.x;
    red[t] = v; __syncthreads();
    #pragma unroll
    for (int o = 128; o > 0; o >>= 1) {
        if (t < o) red[t] += red[t + o];
        __syncthreads();
    }
    float r = red[0]; __syncthreads();
    return r;
}

__device__ __forceinline__ float block_max256(float v, float* red) {
    int t = threadIdx.x;
    red[t] = v; __syncthreads();
    #pragma unroll
    for (int o = 128; o > 0; o >>= 1) {
        if (t < o) red[t] = fmaxf(red[t], red[t + o]);
        __syncthreads();
    }
    float r = red[0]; __syncthreads();
    return r;
}

// ---------------- K1: prep (gw, sgw, bconst, wv_sum) ------------------------
__global__ void prep_kernel(const float* __restrict__ Wv,
                            const float* __restrict__ gp,
                            const float* __restrict__ bp,
                            const float* __restrict__ Wpt,
                            const float* __restrict__ bpt,
                            const float* __restrict__ Wph) {
    __shared__ float red[256];
    int t = threadIdx.x;

    float s = 0.f;
    #pragma unroll 4
    for (int a = 0; a < AD; a++) s += Wv[t*AD + a];
    d_wvsum[t] = s;

    float we = 0.f;
    if (t < DP) {
        #pragma unroll 4
        for (int p = 0; p < PD; p++) we += Wpt[t*PD + p] * Wph[p];
        d_gw[t] = gp[t] * we;
    }
    float v_sgw = (t < DP) ? gp[t] * we : 0.f;
    float v_bc  = (t < DP) ? bp[t] * we : 0.f;
    float v_bpt = (t < PD) ? bpt[t] * Wph[t] : 0.f;

    float sgw = block_sum256(v_sgw, red);
    float bc  = block_sum256(v_bc + v_bpt, red);
    if (t == 0) { d_sgw = sgw; d_bconst = bc; }
}

// ---------------- K0: M = Wq @ Wk^T  (256x256, K=256, NT) -------------------
__global__ void __launch_bounds__(256)
mgemm_kernel(const float* __restrict__ Wq, const float* __restrict__ Wk) {
    __shared__ float As[16][68];
    __shared__ float Bs[16][68];
    int f0 = blockIdx.y * 64;
    int g0 = blockIdx.x * 64;
    int tid = threadIdx.x;
    int lm = tid >> 2;
    int lk = (tid & 3) * 4;
    int ty = tid >> 4, tx = tid & 15;

    float acc[4][4] = {};
    for (int kt = 0; kt < AD; kt += 16) {
        // Wq[f, a] with f rows, a = k dim (row-major stride AD)
        float4 a = *(const float4*)&Wq[(f0 + lm)*AD + kt + lk];
        As[lk+0][lm] = a.x; As[lk+1][lm] = a.y;
        As[lk+2][lm] = a.z; As[lk+3][lm] = a.w;
        float4 c = *(const float4*)&Wk[(g0 + lm)*AD + kt + lk];
        Bs[lk+0][lm] = c.x; Bs[lk+1][lm] = c.y;
        Bs[lk+2][lm] = c.z; Bs[lk+3][lm] = c.w;
        __syncthreads();
        #pragma unroll
        for (int kf = 0; kf < 16; kf++) {
            float4 av = *(const float4*)&As[kf][ty*4];
            float4 bv = *(const float4*)&Bs[kf][tx*4];
            float aa[4] = {av.x, av.y, av.z, av.w};
            float bb[4] = {bv.x, bv.y, bv.z, bv.w};
            #pragma unroll
            for (int i = 0; i < 4; i++)
                #pragma unroll
                for (int j = 0; j < 4; j++)
                    acc[i][j] += aa[i] * bb[j];
        }
        __syncthreads();
    }
    #pragma unroll
    for (int i = 0; i < 4; i++)
        #pragma unroll
        for (int j = 0; j < 4; j++)
            d_M[(f0 + ty*4 + i)*FD + g0 + tx*4 + j] = acc[i][j];
}

// ---------------- K2: LayerNorm(F) -> Fn, vsum ------------------------------
__global__ void lnf_kernel(const float* __restrict__ F,
                           const float* __restrict__ gf,
                           const float* __restrict__ bf) {
    __shared__ float red[256];
    int r = blockIdx.x;
    int t = threadIdx.x;
    float x  = F[r*FD + t];
    float mu = block_sum256(x, red) * (1.f/FD);
    float sq = block_sum256(x*x, red) * (1.f/FD);
    float rstd = rsqrtf(sq - mu*mu + EPSF);
    float fn = (x - mu) * rstd * gf[t] + bf[t];
    d_Fn[r*FD + t] = fn;
    float vs = block_sum256(fn * d_wvsum[t], red);
    if (t == 0) d_vsum[r] = vs;
}

// ---------------- K3: fused  bias(D sweep)  ||  T = Fn @ M ------------------
// blocks [0, BIAS_BLOCKS)           : D sweep (HBM-bound) -- launched first
// blocks [BIAS_BLOCKS, +T_TILES)    : T gemm (compute-bound, hidden)
__global__ void __launch_bounds__(256)
bias_t_kernel(const float* __restrict__ Dm) {
    __shared__ float As[16][68];
    __shared__ float Bs[16][68];
    __shared__ float gwsh[DP];
    int tid = threadIdx.x;

    if (blockIdx.x < BIAS_BLOCKS) {
        // ---- bias: per pair-row LN(64) folded with w_eff ----
        if (tid < DP) gwsh[tid] = d_gw[tid];
        __syncthreads();
        int bb = blockIdx.x;
        int h = tid >> 4;                  // half-warp id 0..15
        int l = tid & 15;                  // lane in half-warp
        float gw0 = gwsh[l*4+0], gw1 = gwsh[l*4+1];
        float gw2 = gwsh[l*4+2], gw3 = gwsh[l*4+3];
        float sgw = d_sgw, bconst = d_bconst;
        int base = bb * 128;

        float4 v[8];
        #pragma unroll
        for (int it = 0; it < 8; it++) {
            int row = base + it*16 + h;
            v[it] = __ldcs((const float4*)&Dm[(size_t)row*DP + l*4]);
        }
        #pragma unroll
        for (int it = 0; it < 8; it++) {
            int row = base + it*16 + h;
            float s1 = v[it].x + v[it].y + v[it].z + v[it].w;
            float s2 = v[it].x*v[it].x + v[it].y*v[it].y
                     + v[it].z*v[it].z + v[it].w*v[it].w;
            float s3 = v[it].x*gw0 + v[it].y*gw1 + v[it].z*gw2 + v[it].w*gw3;
            #pragma unroll
            for (int o = 8; o > 0; o >>= 1) {
                s1 += __shfl_down_sync(0xffffffffu, s1, o, 16);
                s2 += __shfl_down_sync(0xffffffffu, s2, o, 16);
                s3 += __shfl_down_sync(0xffffffffu, s3, o, 16);
            }
            if (l == 0) {
                float mu = s1 * (1.f/DP);
                float var = s2 * (1.f/DP) - mu*mu;
                float rstd = rsqrtf(var + EPSF);
                d_bias[row] = rstd * (s3 - mu*sgw) + bconst;
            }
        }
    } else {
        // ---- T[2048 x 256] = Fn[2048 x 256] @ M[256 x 256] (NN) ----
        int t2 = blockIdx.x - BIAS_BLOCKS;
        int bm = t2 & 31;                  // 32 M tiles
        int bn = t2 >> 5;                  // 4 N tiles
        int row0 = bm * 64;
        int n0   = bn * 64;

        int lm = tid >> 2;
        int lk = (tid & 3) * 4;
        int bk = tid >> 4;                 // 0..15 (M k-row)
        int bn4 = (tid & 15) * 4;
        int ty = tid >> 4, tx = tid & 15;

        float acc[4][4] = {};
        for (int kt = 0; kt < FD; kt += 16) {
            float4 a = *(const float4*)&d_Fn[(row0 + lm)*FD + kt + lk];
            As[lk+0][lm] = a.x; As[lk+1][lm] = a.y;
            As[lk+2][lm] = a.z; As[lk+3][lm] = a.w;
            float4 b = *(const float4*)&d_M[(kt + bk)*FD + n0 + bn4];
            Bs[bk][bn4+0] = b.x; Bs[bk][bn4+1] = b.y;
            Bs[bk][bn4+2] = b.z; Bs[bk][bn4+3] = b.w;
            __syncthreads();
            #pragma unroll
            for (int kf = 0; kf < 16; kf++) {
                float4 av = *(const float4*)&As[kf][ty*4];
                float4 bv = *(const float4*)&Bs[kf][tx*4];
                float aa[4] = {av.x, av.y, av.z, av.w};
                float bb[4] = {bv.x, bv.y, bv.z, bv.w};
                #pragma unroll
                for (int i = 0; i < 4; i++)
                    #pragma unroll
                    for (int j = 0; j < 4; j++)
                        acc[i][j] += aa[i] * bb[j];
            }
            __syncthreads();
        }
        #pragma unroll
        for (int i = 0; i < 4; i++) {
            int r = row0 + ty*4 + i;
            #pragma unroll
            for (int j = 0; j < 4; j++)
                d_T[r*FD + n0 + tx*4 + j] = acc[i][j];
        }
    }
}

// ---------------- K4: S = SCAL * (T @ Fn^T + bias)  (batched NT GEMM) -------
// tiles 32(q) x 64(k), 128 threads, grid (8, 16, 4) = 512 blocks
__global__ void __launch_bounds__(128)
s_gemm_kernel() {
    __shared__ float As[16][36];   // 36*4=144, 16B-aligned rows
    __shared__ float Bs[16][68];   // 68*4=272, 16B-aligned rows
    int b  = blockIdx.z;
    int q0 = blockIdx.y * 32;
    int k0 = blockIdx.x * 64;
    const float* A  = d_T  + b*NN*FD;   // [512 x 256]
    const float* Bm = d_Fn + b*NN*FD;   // [512 x 256]

    int tid = threadIdx.x;
    int lm = tid >> 2;                  // 0..31
    int lk = (tid & 3) * 4;             // 0,4,8,12
    int ty = tid >> 4, tx = tid & 15;   // ty 0..7, tx 0..15

    float acc[4][4] = {};
    for (int kt = 0; kt < FD; kt += 16) {
        float4 a = *(const float4*)&A[(q0 + lm)*FD + kt + lk];
        As[lk+0][lm] = a.x; As[lk+1][lm] = a.y;
        As[lk+2][lm] = a.z; As[lk+3][lm] = a.w;
        float4 c0 = *(const float4*)&Bm[(k0 + lm)*FD + kt + lk];
        Bs[lk+0][lm] = c0.x; Bs[lk+1][lm] = c0.y;
        Bs[lk+2][lm] = c0.z; Bs[lk+3][lm] = c0.w;
        float4 c1 = *(const float4*)&Bm[(k0 + 32 + lm)*FD + kt + lk];
        Bs[lk+0][lm+32] = c1.x; Bs[lk+1][lm+32] = c1.y;
        Bs[lk+2][lm+32] = c1.z; Bs[lk+3][lm+32] = c1.w;
        __syncthreads();
        #pragma unroll
        for (int kf = 0; kf < 16; kf++) {
            float4 av = *(const float4*)&As[kf][ty*4];
            float4 bv = *(const float4*)&Bs[kf][tx*4];
            float aa[4] = {av.x, av.y, av.z, av.w};
            float bb[4] = {bv.x, bv.y, bv.z, bv.w};
            #pragma unroll
            for (int i = 0; i < 4; i++)
                #pragma unroll
                for (int j = 0; j < 4; j++)
                    acc[i][j] += aa[i] * bb[j];
        }
        __syncthreads();
    }
    #pragma unroll
    for (int i = 0; i < 4; i++) {
        int q = q0 + ty*4 + i;
        int idx = (b*NN + q)*NN + k0 + tx*4;
        float4 bi = *(const float4*)&d_bias[idx];
        float4 o;
        o.x = SCAL * (acc[i][0] + bi.x);
        o.y = SCAL * (acc[i][1] + bi.y);
        o.z = SCAL * (acc[i][2] + bi.z);
        o.w = SCAL * (acc[i][3] + bi.w);
        *(float4*)&d_S[idx] = o;
    }
}

// ---------------- K5: softmax over k + dot with vsum ------------------------
__global__ void softmax_out_kernel(float* __restrict__ out) {
    __shared__ float red[256];
    int r = blockIdx.x;          // 0..2047 = b*512 + q
    int b = r >> 9;
    int t = threadIdx.x;
    float s0 = d_S[r*NN + t];
    float s1 = d_S[r*NN + 256 + t];
    float m = block_max256(fmaxf(s0, s1), red);
    float e0 = expf(s0 - m), e1 = expf(s1 - m);
    float v0 = d_vsum[b*NN + t], v1 = d_vsum[b*NN + 256 + t];
    float se = block_sum256(e0 + e1, red);
    float sv = block_sum256(e0*v0 + e1*v1, red);
    if (t == 0) out[r] = sv / se;
}

// ---------------- launch ----------------------------------------------------
extern "C" void kernel_launch(void* const* d_in, const int* in_sizes, int n_in,
                              void* d_out, int out_size) {
    const float* F   = (const float*)d_in[0];
    const float* Dm  = (const float*)d_in[1];
    const float* Wq  = (const float*)d_in[2];
    const float* Wk  = (const float*)d_in[3];
    const float* Wv  = (const float*)d_in[4];
    const float* gf  = (const float*)d_in[5];
    const float* bf  = (const float*)d_in[6];
    const float* gp  = (const float*)d_in[7];
    const float* bp  = (const float*)d_in[8];
    const float* Wpt = (const float*)d_in[9];
    const float* bpt = (const float*)d_in[10];
    const float* Wph = (const float*)d_in[11];
    float* out = (float*)d_out;

    mgemm_kernel<<<dim3(4, 4), 256>>>(Wq, Wk);
    prep_kernel<<<1, 256>>>(Wv, gp, bp, Wpt, bpt, Wph);
    lnf_kernel<<<ROWS, 256>>>(F, gf, bf);
    bias_t_kernel<<<BIAS_BLOCKS + T_TILES, 256>>>(Dm);
    dim3 g4(NN/64, NN/32, BB);
    s_gemm_kernel<<<g4, 128>>>();
    softmax_out_kernel<<<ROWS, 256>>>(out);
}

// round 4
// speedup vs baseline: 1.6047x; 1.6047x over previous
#include <cuda_runtime.h>

#define BB   4
#define NN   512
#define FD   256
#define AD   256
#define DP   64
#define PD   128
#define ROWS (BB*NN)          /* 2048 */
#define NPAIR (BB*NN*NN)      /* 1048576 */
#define EPSF 1e-3f
#define SCAL 0.0625f          /* 1/sqrt(256) */

#define BIAS_BLOCKS 4096      /* 1048576 rows / 256 rows per block */
#define T_TILES     128       /* (2048/64) * (256/64) */

// ---------------- scratch (device globals; no allocation allowed) ----------
__device__ float d_Fn[ROWS*FD];
__device__ float d_M[FD*FD];         // Wq @ Wk^T
__device__ float d_T[ROWS*FD];       // Fn @ M
__device__ float d_vsum[ROWS];
__device__ float d_gw[DP];
__device__ float d_sgw;
__device__ float d_bconst;
__device__ float d_wvsum[FD];
__device__ float d_bias[NPAIR];
__device__ float d_S[NPAIR];

// ---------------- helpers ---------------------------------------------------
__device__ __forceinline__ float warp_sum(float v) {
    #pragma unroll
    for (int o = 16; o > 0; o >>= 1) v += __shfl_xor_sync(0xffffffffu, v, o);
    return v;
}
__device__ __forceinline__ float warp_max(float v) {
    #pragma unroll
    for (int o = 16; o > 0; o >>= 1) v = fmaxf(v, __shfl_xor_sync(0xffffffffu, v, o));
    return v;
}

// legacy ladder (used only in tiny prep kernel)
__device__ __forceinline__ float block_sum256(float v, float* red) {
    int t = threadIdx.x;
    red[t] = v; __syncthreads();
    #pragma unroll
    for (int o = 128; o > 0; o >>= 1) {
        if (t < o) red[t] += red[t + o];
        __syncthreads();
    }
    float r = red[0]; __syncthreads();
    return r;
}

// ---------------- K1: prep (gw, sgw, bconst, wv_sum) ------------------------
__global__ void prep_kernel(const float* __restrict__ Wv,
                            const float* __restrict__ gp,
                            const float* __restrict__ bp,
                            const float* __restrict__ Wpt,
                            const float* __restrict__ bpt,
                            const float* __restrict__ Wph) {
    __shared__ float red[256];
    int t = threadIdx.x;

    float s = 0.f;
    #pragma unroll 4
    for (int a = 0; a < AD; a++) s += Wv[t*AD + a];
    d_wvsum[t] = s;

    float we = 0.f;
    if (t < DP) {
        #pragma unroll 4
        for (int p = 0; p < PD; p++) we += Wpt[t*PD + p] * Wph[p];
        d_gw[t] = gp[t] * we;
    }
    float v_sgw = (t < DP) ? gp[t] * we : 0.f;
    float v_bc  = (t < DP) ? bp[t] * we : 0.f;
    float v_bpt = (t < PD) ? bpt[t] * Wph[t] : 0.f;

    float sgw = block_sum256(v_sgw, red);
    float bc  = block_sum256(v_bc + v_bpt, red);
    if (t == 0) { d_sgw = sgw; d_bconst = bc; }
}

// ---------------- K0: M = Wq @ Wk^T  (256x256, K=256, NT) -------------------
__global__ void __launch_bounds__(256)
mgemm_kernel(const float* __restrict__ Wq, const float* __restrict__ Wk) {
    __shared__ float As[16][68];
    __shared__ float Bs[16][68];
    int f0 = blockIdx.y * 64;
    int g0 = blockIdx.x * 64;
    int tid = threadIdx.x;
    int lm = tid >> 2;
    int lk = (tid & 3) * 4;
    int ty = tid >> 4, tx = tid & 15;

    float acc[4][4] = {};
    for (int kt = 0; kt < AD; kt += 16) {
        float4 a = *(const float4*)&Wq[(f0 + lm)*AD + kt + lk];
        As[lk+0][lm] = a.x; As[lk+1][lm] = a.y;
        As[lk+2][lm] = a.z; As[lk+3][lm] = a.w;
        float4 c = *(const float4*)&Wk[(g0 + lm)*AD + kt + lk];
        Bs[lk+0][lm] = c.x; Bs[lk+1][lm] = c.y;
        Bs[lk+2][lm] = c.z; Bs[lk+3][lm] = c.w;
        __syncthreads();
        #pragma unroll
        for (int kf = 0; kf < 16; kf++) {
            float4 av = *(const float4*)&As[kf][ty*4];
            float4 bv = *(const float4*)&Bs[kf][tx*4];
            float aa[4] = {av.x, av.y, av.z, av.w};
            float bb[4] = {bv.x, bv.y, bv.z, bv.w};
            #pragma unroll
            for (int i = 0; i < 4; i++)
                #pragma unroll
                for (int j = 0; j < 4; j++)
                    acc[i][j] += aa[i] * bb[j];
        }
        __syncthreads();
    }
    #pragma unroll
    for (int i = 0; i < 4; i++)
        #pragma unroll
        for (int j = 0; j < 4; j++)
            d_M[(f0 + ty*4 + i)*FD + g0 + tx*4 + j] = acc[i][j];
}

// ---------------- K2: LayerNorm(F) -> Fn, vsum ------------------------------
__global__ void __launch_bounds__(256)
lnf_kernel(const float* __restrict__ F,
           const float* __restrict__ gf,
           const float* __restrict__ bf) {
    __shared__ float s_a[8], s_b[8];
    int r = blockIdx.x;
    int t = threadIdx.x;
    int w = t >> 5, l = t & 31;
    float x = F[r*FD + t];

    float sa = warp_sum(x);
    float sb = warp_sum(x*x);
    if (l == 0) { s_a[w] = sa; s_b[w] = sb; }
    __syncthreads();
    float ts = 0.f, tq = 0.f;
    #pragma unroll
    for (int i = 0; i < 8; i++) { ts += s_a[i]; tq += s_b[i]; }
    float mu = ts * (1.f/FD);
    float rstd = rsqrtf(tq * (1.f/FD) - mu*mu + EPSF);
    float fn = (x - mu) * rstd * gf[t] + bf[t];
    d_Fn[r*FD + t] = fn;

    __syncthreads();
    float sv = warp_sum(fn * d_wvsum[t]);
    if (l == 0) s_a[w] = sv;
    __syncthreads();
    if (t == 0) {
        float acc = 0.f;
        #pragma unroll
        for (int i = 0; i < 8; i++) acc += s_a[i];
        d_vsum[r] = acc;
    }
}

// ---------------- K3: fused  bias(D sweep)  ||  T = Fn @ M ------------------
// bias: 4 lanes per 64-float row -> 8 rows/warp, 2-step width-4 shuffles.
__global__ void __launch_bounds__(256)
bias_t_kernel(const float* __restrict__ Dm) {
    int tid = threadIdx.x;

    if (blockIdx.x < BIAS_BLOCKS) {
        int w = tid >> 5, l = tid & 31;
        int sub = l & 3;          // lane's column group (4 slots of float4)
        int rr  = l >> 2;         // row within warp group (0..7)

        // gw slots for this lane: float4 slots {sub, sub+4, sub+8, sub+12}
        float4 g0 = *(const float4*)&d_gw[(sub     )*4];
        float4 g1 = *(const float4*)&d_gw[(sub +  4)*4];
        float4 g2 = *(const float4*)&d_gw[(sub +  8)*4];
        float4 g3 = *(const float4*)&d_gw[(sub + 12)*4];
        float sgw = d_sgw, bconst = d_bconst;

        int base = blockIdx.x * 256 + w * 8 + rr;
        #pragma unroll
        for (int it = 0; it < 4; it++) {
            int row = base + it * 64;
            const float4* p = (const float4*)&Dm[(size_t)row * DP];
            float4 v0 = __ldcs(p + sub);
            float4 v1 = __ldcs(p + sub + 4);
            float4 v2 = __ldcs(p + sub + 8);
            float4 v3 = __ldcs(p + sub + 12);

            float s1 = (v0.x+v0.y+v0.z+v0.w) + (v1.x+v1.y+v1.z+v1.w)
                     + (v2.x+v2.y+v2.z+v2.w) + (v3.x+v3.y+v3.z+v3.w);
            float s2 = v0.x*v0.x+v0.y*v0.y+v0.z*v0.z+v0.w*v0.w
                     + v1.x*v1.x+v1.y*v1.y+v1.z*v1.z+v1.w*v1.w
                     + v2.x*v2.x+v2.y*v2.y+v2.z*v2.z+v2.w*v2.w
                     + v3.x*v3.x+v3.y*v3.y+v3.z*v3.z+v3.w*v3.w;
            float s3 = v0.x*g0.x+v0.y*g0.y+v0.z*g0.z+v0.w*g0.w
                     + v1.x*g1.x+v1.y*g1.y+v1.z*g1.z+v1.w*g1.w
                     + v2.x*g2.x+v2.y*g2.y+v2.z*g2.z+v2.w*g2.w
                     + v3.x*g3.x+v3.y*g3.y+v3.z*g3.z+v3.w*g3.w;

            // width-4 xor reduction (2 steps), all 8 rows of the warp at once
            #pragma unroll
            for (int o = 1; o < 4; o <<= 1) {
                s1 += __shfl_xor_sync(0xffffffffu, s1, o);
                s2 += __shfl_xor_sync(0xffffffffu, s2, o);
                s3 += __shfl_xor_sync(0xffffffffu, s3, o);
            }
            if (sub == 0) {
                float mu = s1 * (1.f/DP);
                float var = s2 * (1.f/DP) - mu*mu;
                float rstd = rsqrtf(var + EPSF);
                d_bias[row] = rstd * (s3 - mu*sgw) + bconst;
            }
        }
    } else {
        // ---- T[2048 x 256] = Fn[2048 x 256] @ M[256 x 256] (NN) ----
        __shared__ float As[16][68];
        __shared__ float Bs[16][68];
        int t2 = blockIdx.x - BIAS_BLOCKS;
        int bm = t2 & 31;
        int bn = t2 >> 5;
        int row0 = bm * 64;
        int n0   = bn * 64;

        int lm = tid >> 2;
        int lk = (tid & 3) * 4;
        int bk = tid >> 4;
        int bn4 = (tid & 15) * 4;
        int ty = tid >> 4, tx = tid & 15;

        float acc[4][4] = {};
        for (int kt = 0; kt < FD; kt += 16) {
            float4 a = *(const float4*)&d_Fn[(row0 + lm)*FD + kt + lk];
            As[lk+0][lm] = a.x; As[lk+1][lm] = a.y;
            As[lk+2][lm] = a.z; As[lk+3][lm] = a.w;
            float4 b = *(const float4*)&d_M[(kt + bk)*FD + n0 + bn4];
            Bs[bk][bn4+0] = b.x; Bs[bk][bn4+1] = b.y;
            Bs[bk][bn4+2] = b.z; Bs[bk][bn4+3] = b.w;
            __syncthreads();
            #pragma unroll
            for (int kf = 0; kf < 16; kf++) {
                float4 av = *(const float4*)&As[kf][ty*4];
                float4 bv = *(const float4*)&Bs[kf][tx*4];
                float aa[4] = {av.x, av.y, av.z, av.w};
                float bb[4] = {bv.x, bv.y, bv.z, bv.w};
                #pragma unroll
                for (int i = 0; i < 4; i++)
                    #pragma unroll
                    for (int j = 0; j < 4; j++)
                        acc[i][j] += aa[i] * bb[j];
            }
            __syncthreads();
        }
        #pragma unroll
        for (int i = 0; i < 4; i++) {
            int r = row0 + ty*4 + i;
            #pragma unroll
            for (int j = 0; j < 4; j++)
                d_T[r*FD + n0 + tx*4 + j] = acc[i][j];
        }
    }
}

// ---------------- K4: S = SCAL * (T @ Fn^T + bias)  (R1-proven 64x64 tile) --
__global__ void __launch_bounds__(256)
s_gemm_kernel() {
    __shared__ float As[16][68];
    __shared__ float Bs[16][68];
    int b  = blockIdx.z;
    int q0 = blockIdx.y * 64;
    int k0 = blockIdx.x * 64;
    const float* A  = d_T  + b*NN*FD;
    const float* Bm = d_Fn + b*NN*FD;

    int tid = threadIdx.x;
    int lm = tid >> 2;
    int lk = (tid & 3) * 4;
    int ty = tid >> 4, tx = tid & 15;

    float acc[4][4] = {};
    for (int kt = 0; kt < FD; kt += 16) {
        float4 a = *(const float4*)&A[(q0 + lm)*FD + kt + lk];
        As[lk+0][lm] = a.x; As[lk+1][lm] = a.y;
        As[lk+2][lm] = a.z; As[lk+3][lm] = a.w;
        float4 c = *(const float4*)&Bm[(k0 + lm)*FD + kt + lk];
        Bs[lk+0][lm] = c.x; Bs[lk+1][lm] = c.y;
        Bs[lk+2][lm] = c.z; Bs[lk+3][lm] = c.w;
        __syncthreads();
        #pragma unroll
        for (int kf = 0; kf < 16; kf++) {
            float4 av = *(const float4*)&As[kf][ty*4];
            float4 bv = *(const float4*)&Bs[kf][tx*4];
            float aa[4] = {av.x, av.y, av.z, av.w};
            float bb[4] = {bv.x, bv.y, bv.z, bv.w};
            #pragma unroll
            for (int i = 0; i < 4; i++)
                #pragma unroll
                for (int j = 0; j < 4; j++)
                    acc[i][j] += aa[i] * bb[j];
        }
        __syncthreads();
    }
    #pragma unroll
    for (int i = 0; i < 4; i++) {
        int q = q0 + ty*4 + i;
        int idx = (b*NN + q)*NN + k0 + tx*4;
        float4 bi = *(const float4*)&d_bias[idx];
        float4 o;
        o.x = SCAL * (acc[i][0] + bi.x);
        o.y = SCAL * (acc[i][1] + bi.y);
        o.z = SCAL * (acc[i][2] + bi.z);
        o.w = SCAL * (acc[i][3] + bi.w);
        *(float4*)&d_S[idx] = o;
    }
}

// ---------------- K5: softmax over k + dot with vsum ------------------------
__global__ void __launch_bounds__(256)
softmax_out_kernel(float* __restrict__ out) {
    __shared__ float s_a[8], s_b[8];
    int r = blockIdx.x;
    int b = r >> 9;
    int t = threadIdx.x;
    int w = t >> 5, l = t & 31;

    float s0 = d_S[r*NN + t];
    float s1 = d_S[r*NN + 256 + t];
    float wm = warp_max(fmaxf(s0, s1));
    if (l == 0) s_a[w] = wm;
    __syncthreads();
    float m = s_a[0];
    #pragma unroll
    for (int i = 1; i < 8; i++) m = fmaxf(m, s_a[i]);

    float e0 = __expf(s0 - m), e1 = __expf(s1 - m);
    float v0 = d_vsum[b*NN + t], v1 = d_vsum[b*NN + 256 + t];
    __syncthreads();
    float se = warp_sum(e0 + e1);
    float sv = warp_sum(e0*v0 + e1*v1);
    if (l == 0) { s_a[w] = se; s_b[w] = sv; }
    __syncthreads();
    if (t == 0) {
        float tse = 0.f, tsv = 0.f;
        #pragma unroll
        for (int i = 0; i < 8; i++) { tse += s_a[i]; tsv += s_b[i]; }
        out[r] = tsv / tse;
    }
}

// ---------------- launch ----------------------------------------------------
extern "C" void kernel_launch(void* const* d_in, const int* in_sizes, int n_in,
                              void* d_out, int out_size) {
    const float* F   = (const float*)d_in[0];
    const float* Dm  = (const float*)d_in[1];
    const float* Wq  = (const float*)d_in[2];
    const float* Wk  = (const float*)d_in[3];
    const float* Wv  = (const float*)d_in[4];
    const float* gf  = (const float*)d_in[5];
    const float* bf  = (const float*)d_in[6];
    const float* gp  = (const float*)d_in[7];
    const float* bp  = (const float*)d_in[8];
    const float* Wpt = (const float*)d_in[9];
    const float* bpt = (const float*)d_in[10];
    const float* Wph = (const float*)d_in[11];
    float* out = (float*)d_out;

    mgemm_kernel<<<dim3(4, 4), 256>>>(Wq, Wk);
    prep_kernel<<<1, 256>>>(Wv, gp, bp, Wpt, bpt, Wph);
    lnf_kernel<<<ROWS, 256>>>(F, gf, bf);
    bias_t_kernel<<<BIAS_BLOCKS + T_TILES, 256>>>(Dm);
    dim3 g4(NN/64, NN/64, BB);
    s_gemm_kernel<<<g4, 256>>>();
    softmax_out_kernel<<<ROWS, 256>>>(out);
}

// round 5
// speedup vs baseline: 2.1105x; 1.3152x over previous
#include <cuda_runtime.h>

#define BB   4
#define NN   512
#define FD   256
#define AD   256
#define DP   64
#define PD   128
#define ROWS (BB*NN)          /* 2048 */
#define NPAIR (BB*NN*NN)      /* 1048576 */
#define EPSF 1e-3f
#define SCAL 0.0625f          /* 1/sqrt(256) */

#define BIAS_BLOCKS 4096      /* 1048576 rows / 256 rows per block */
#define T_TILES     128       /* (2048/64) * (256/64) */

// ---------------- scratch (device globals; no allocation allowed) ----------
__device__ float d_Fn[ROWS*FD];
__device__ float d_M[FD*FD];         // Wq @ Wk^T
__device__ float d_T[ROWS*FD];       // Fn @ M
__device__ float d_vsum[ROWS];
__device__ float d_gw[DP];
__device__ float d_sgw;
__device__ float d_bconst;
__device__ float d_wvsum[FD];
__device__ float d_bias[NPAIR];
__device__ float d_S[NPAIR];

// ---------------- helpers ---------------------------------------------------
__device__ __forceinline__ float warp_sum(float v) {
    #pragma unroll
    for (int o = 16; o > 0; o >>= 1) v += __shfl_xor_sync(0xffffffffu, v, o);
    return v;
}
__device__ __forceinline__ float warp_max(float v) {
    #pragma unroll
    for (int o = 16; o > 0; o >>= 1) v = fmaxf(v, __shfl_xor_sync(0xffffffffu, v, o));
    return v;
}

// ---------------- K1: prep (grid 257 x 128 threads) -------------------------
// blocks 0..255  : wvsum[f] = sum_a Wv[f, a]   (coalesced row sum)
// block  256     : gw, sgw, bconst
__global__ void __launch_bounds__(128)
prep_kernel(const float* __restrict__ Wv,
            const float* __restrict__ gp,
            const float* __restrict__ bp,
            const float* __restrict__ Wpt,
            const float* __restrict__ bpt,
            const float* __restrict__ Wph) {
    int t = threadIdx.x;
    int w = t >> 5, l = t & 31;

    if (blockIdx.x < 256) {
        int f = blockIdx.x;
        __shared__ float s_w[4];
        float2 v = *(const float2*)&Wv[f*AD + t*2];
        float s = warp_sum(v.x + v.y);
        if (l == 0) s_w[w] = s;
        __syncthreads();
        if (t == 0) d_wvsum[f] = s_w[0] + s_w[1] + s_w[2] + s_w[3];
        return;
    }

    // block 256: per-channel effective weight
    __shared__ float red[128];
    int c = t >> 1;              // 0..63
    int j = t & 1;               // half of PD
    float we = 0.f;
    #pragma unroll
    for (int i = 0; i < 16; i++) {
        float4 a = *(const float4*)&Wpt[c*PD + j*64 + i*4];
        float4 b = *(const float4*)&Wph[j*64 + i*4];
        we += a.x*b.x + a.y*b.y + a.z*b.z + a.w*b.w;
    }
    we += __shfl_xor_sync(0xffffffffu, we, 1);
    if (j == 0) d_gw[c] = gp[c] * we;

    float v_sgw = (j == 0) ? gp[c] * we : 0.f;
    float v_bc  = (j == 0) ? bp[c] * we : 0.f;
    float v_bpt = bpt[t] * Wph[t];          // t covers 0..127 = PD

    red[t] = v_sgw; __syncthreads();
    #pragma unroll
    for (int o = 64; o > 0; o >>= 1) { if (t < o) red[t] += red[t+o]; __syncthreads(); }
    if (t == 0) d_sgw = red[0];
    __syncthreads();
    red[t] = v_bc + v_bpt; __syncthreads();
    #pragma unroll
    for (int o = 64; o > 0; o >>= 1) { if (t < o) red[t] += red[t+o]; __syncthreads(); }
    if (t == 0) d_bconst = red[0];
}

// ---------------- K0: M = Wq @ Wk^T  (256x256, K=256, NT) -------------------
__global__ void __launch_bounds__(256)
mgemm_kernel(const float* __restrict__ Wq, const float* __restrict__ Wk) {
    __shared__ float As[16][68];
    __shared__ float Bs[16][68];
    int f0 = blockIdx.y * 64;
    int g0 = blockIdx.x * 64;
    int tid = threadIdx.x;
    int lm = tid >> 2;
    int lk = (tid & 3) * 4;
    int ty = tid >> 4, tx = tid & 15;

    float acc[4][4] = {};
    for (int kt = 0; kt < AD; kt += 16) {
        float4 a = *(const float4*)&Wq[(f0 + lm)*AD + kt + lk];
        As[lk+0][lm] = a.x; As[lk+1][lm] = a.y;
        As[lk+2][lm] = a.z; As[lk+3][lm] = a.w;
        float4 c = *(const float4*)&Wk[(g0 + lm)*AD + kt + lk];
        Bs[lk+0][lm] = c.x; Bs[lk+1][lm] = c.y;
        Bs[lk+2][lm] = c.z; Bs[lk+3][lm] = c.w;
        __syncthreads();
        #pragma unroll
        for (int kf = 0; kf < 16; kf++) {
            float4 av = *(const float4*)&As[kf][ty*4];
            float4 bv = *(const float4*)&Bs[kf][tx*4];
            float aa[4] = {av.x, av.y, av.z, av.w};
            float bb[4] = {bv.x, bv.y, bv.z, bv.w};
            #pragma unroll
            for (int i = 0; i < 4; i++)
                #pragma unroll
                for (int j = 0; j < 4; j++)
                    acc[i][j] += aa[i] * bb[j];
        }
        __syncthreads();
    }
    #pragma unroll
    for (int i = 0; i < 4; i++)
        #pragma unroll
        for (int j = 0; j < 4; j++)
            d_M[(f0 + ty*4 + i)*FD + g0 + tx*4 + j] = acc[i][j];
}

// ---------------- K2: LayerNorm(F) -> Fn, vsum ------------------------------
__global__ void __launch_bounds__(256)
lnf_kernel(const float* __restrict__ F,
           const float* __restrict__ gf,
           const float* __restrict__ bf) {
    __shared__ float s_a[8], s_b[8];
    int r = blockIdx.x;
    int t = threadIdx.x;
    int w = t >> 5, l = t & 31;
    float x = F[r*FD + t];

    float sa = warp_sum(x);
    float sb = warp_sum(x*x);
    if (l == 0) { s_a[w] = sa; s_b[w] = sb; }
    __syncthreads();
    float ts = 0.f, tq = 0.f;
    #pragma unroll
    for (int i = 0; i < 8; i++) { ts += s_a[i]; tq += s_b[i]; }
    float mu = ts * (1.f/FD);
    float rstd = rsqrtf(tq * (1.f/FD) - mu*mu + EPSF);
    float fn = (x - mu) * rstd * gf[t] + bf[t];
    d_Fn[r*FD + t] = fn;

    __syncthreads();
    float sv = warp_sum(fn * d_wvsum[t]);
    if (l == 0) s_a[w] = sv;
    __syncthreads();
    if (t == 0) {
        float acc = 0.f;
        #pragma unroll
        for (int i = 0; i < 8; i++) acc += s_a[i];
        d_vsum[r] = acc;
    }
}

// ---------------- K3: fused  bias(D sweep, pipelined)  ||  T = Fn @ M -------
__global__ void __launch_bounds__(256)
bias_t_kernel(const float* __restrict__ Dm) {
    int tid = threadIdx.x;

    if (blockIdx.x < BIAS_BLOCKS) {
        int w = tid >> 5, l = tid & 31;
        int sub = l & 3;          // lane's column group (4 float4 slots)
        int rr  = l >> 2;         // row within warp group (0..7)

        float4 g0 = *(const float4*)&d_gw[(sub     )*4];
        float4 g1 = *(const float4*)&d_gw[(sub +  4)*4];
        float4 g2 = *(const float4*)&d_gw[(sub +  8)*4];
        float4 g3 = *(const float4*)&d_gw[(sub + 12)*4];
        float sgw = d_sgw, bconst = d_bconst;

        int base = blockIdx.x * 256 + w * 8 + rr;

        // software pipeline: preload next row-group before reducing current
        const float4* p = (const float4*)&Dm[(size_t)base * DP];
        float4 c0 = __ldcs(p + sub);
        float4 c1 = __ldcs(p + sub + 4);
        float4 c2 = __ldcs(p + sub + 8);
        float4 c3 = __ldcs(p + sub + 12);

        #pragma unroll
        for (int it = 0; it < 4; it++) {
            float4 n0, n1, n2, n3;
            if (it < 3) {
                const float4* pn = (const float4*)&Dm[(size_t)(base + (it+1)*64) * DP];
                n0 = __ldcs(pn + sub);
                n1 = __ldcs(pn + sub + 4);
                n2 = __ldcs(pn + sub + 8);
                n3 = __ldcs(pn + sub + 12);
            }
            float s1 = (c0.x+c0.y+c0.z+c0.w) + (c1.x+c1.y+c1.z+c1.w)
                     + (c2.x+c2.y+c2.z+c2.w) + (c3.x+c3.y+c3.z+c3.w);
            float s2 = c0.x*c0.x+c0.y*c0.y+c0.z*c0.z+c0.w*c0.w
                     + c1.x*c1.x+c1.y*c1.y+c1.z*c1.z+c1.w*c1.w
                     + c2.x*c2.x+c2.y*c2.y+c2.z*c2.z+c2.w*c2.w
                     + c3.x*c3.x+c3.y*c3.y+c3.z*c3.z+c3.w*c3.w;
            float s3 = c0.x*g0.x+c0.y*g0.y+c0.z*g0.z+c0.w*g0.w
                     + c1.x*g1.x+c1.y*g1.y+c1.z*g1.z+c1.w*g1.w
                     + c2.x*g2.x+c2.y*g2.y+c2.z*g2.z+c2.w*g2.w
                     + c3.x*g3.x+c3.y*g3.y+c3.z*g3.z+c3.w*g3.w;

            #pragma unroll
            for (int o = 1; o < 4; o <<= 1) {
                s1 += __shfl_xor_sync(0xffffffffu, s1, o);
                s2 += __shfl_xor_sync(0xffffffffu, s2, o);
                s3 += __shfl_xor_sync(0xffffffffu, s3, o);
            }
            if (sub == 0) {
                float mu = s1 * (1.f/DP);
                float var = s2 * (1.f/DP) - mu*mu;
                float rstd = rsqrtf(var + EPSF);
                d_bias[base + it*64] = rstd * (s3 - mu*sgw) + bconst;
            }
            c0 = n0; c1 = n1; c2 = n2; c3 = n3;
        }
    } else {
        // ---- T[2048 x 256] = Fn[2048 x 256] @ M[256 x 256] (NN) ----
        __shared__ float As[16][68];
        __shared__ float Bs[16][68];
        int t2 = blockIdx.x - BIAS_BLOCKS;
        int bm = t2 & 31;
        int bn = t2 >> 5;
        int row0 = bm * 64;
        int n0   = bn * 64;

        int lm = tid >> 2;
        int lk = (tid & 3) * 4;
        int bk = tid >> 4;
        int bn4 = (tid & 15) * 4;
        int ty = tid >> 4, tx = tid & 15;

        float acc[4][4] = {};
        for (int kt = 0; kt < FD; kt += 16) {
            float4 a = *(const float4*)&d_Fn[(row0 + lm)*FD + kt + lk];
            As[lk+0][lm] = a.x; As[lk+1][lm] = a.y;
            As[lk+2][lm] = a.z; As[lk+3][lm] = a.w;
            float4 b = *(const float4*)&d_M[(kt + bk)*FD + n0 + bn4];
            Bs[bk][bn4+0] = b.x; Bs[bk][bn4+1] = b.y;
            Bs[bk][bn4+2] = b.z; Bs[bk][bn4+3] = b.w;
            __syncthreads();
            #pragma unroll
            for (int kf = 0; kf < 16; kf++) {
                float4 av = *(const float4*)&As[kf][ty*4];
                float4 bv = *(const float4*)&Bs[kf][tx*4];
                float aa[4] = {av.x, av.y, av.z, av.w};
                float bb[4] = {bv.x, bv.y, bv.z, bv.w};
                #pragma unroll
                for (int i = 0; i < 4; i++)
                    #pragma unroll
                    for (int j = 0; j < 4; j++)
                        acc[i][j] += aa[i] * bb[j];
            }
            __syncthreads();
        }
        #pragma unroll
        for (int i = 0; i < 4; i++) {
            int r = row0 + ty*4 + i;
            #pragma unroll
            for (int j = 0; j < 4; j++)
                d_T[r*FD + n0 + tx*4 + j] = acc[i][j];
        }
    }
}

// ---------------- K4: S = SCAL * (T @ Fn^T + bias) --------------------------
__global__ void __launch_bounds__(256)
s_gemm_kernel() {
    __shared__ float As[16][68];
    __shared__ float Bs[16][68];
    int b  = blockIdx.z;
    int q0 = blockIdx.y * 64;
    int k0 = blockIdx.x * 64;
    const float* A  = d_T  + b*NN*FD;
    const float* Bm = d_Fn + b*NN*FD;

    int tid = threadIdx.x;
    int lm = tid >> 2;
    int lk = (tid & 3) * 4;
    int ty = tid >> 4, tx = tid & 15;

    float acc[4][4] = {};
    for (int kt = 0; kt < FD; kt += 16) {
        float4 a = *(const float4*)&A[(q0 + lm)*FD + kt + lk];
        As[lk+0][lm] = a.x; As[lk+1][lm] = a.y;
        As[lk+2][lm] = a.z; As[lk+3][lm] = a.w;
        float4 c = *(const float4*)&Bm[(k0 + lm)*FD + kt + lk];
        Bs[lk+0][lm] = c.x; Bs[lk+1][lm] = c.y;
        Bs[lk+2][lm] = c.z; Bs[lk+3][lm] = c.w;
        __syncthreads();
        #pragma unroll
        for (int kf = 0; kf < 16; kf++) {
            float4 av = *(const float4*)&As[kf][ty*4];
            float4 bv = *(const float4*)&Bs[kf][tx*4];
            float aa[4] = {av.x, av.y, av.z, av.w};
            float bb[4] = {bv.x, bv.y, bv.z, bv.w};
            #pragma unroll
            for (int i = 0; i < 4; i++)
                #pragma unroll
                for (int j = 0; j < 4; j++)
                    acc[i][j] += aa[i] * bb[j];
        }
        __syncthreads();
    }
    #pragma unroll
    for (int i = 0; i < 4; i++) {
        int q = q0 + ty*4 + i;
        int idx = (b*NN + q)*NN + k0 + tx*4;
        float4 bi = *(const float4*)&d_bias[idx];
        float4 o;
        o.x = SCAL * (acc[i][0] + bi.x);
        o.y = SCAL * (acc[i][1] + bi.y);
        o.z = SCAL * (acc[i][2] + bi.z);
        o.w = SCAL * (acc[i][3] + bi.w);
        *(float4*)&d_S[idx] = o;
    }
}

// ---------------- K5: softmax over k + dot with vsum ------------------------
__global__ void __launch_bounds__(256)
softmax_out_kernel(float* __restrict__ out) {
    __shared__ float s_a[8], s_b[8];
    int r = blockIdx.x;
    int b = r >> 9;
    int t = threadIdx.x;
    int w = t >> 5, l = t & 31;

    float s0 = d_S[r*NN + t];
    float s1 = d_S[r*NN + 256 + t];
    float wm = warp_max(fmaxf(s0, s1));
    if (l == 0) s_a[w] = wm;
    __syncthreads();
    float m = s_a[0];
    #pragma unroll
    for (int i = 1; i < 8; i++) m = fmaxf(m, s_a[i]);

    float e0 = __expf(s0 - m), e1 = __expf(s1 - m);
    float v0 = d_vsum[b*NN + t], v1 = d_vsum[b*NN + 256 + t];
    __syncthreads();
    float se = warp_sum(e0 + e1);
    float sv = warp_sum(e0*v0 + e1*v1);
    if (l == 0) { s_a[w] = se; s_b[w] = sv; }
    __syncthreads();
    if (t == 0) {
        float tse = 0.f, tsv = 0.f;
        #pragma unroll
        for (int i = 0; i < 8; i++) { tse += s_a[i]; tsv += s_b[i]; }
        out[r] = tsv / tse;
    }
}

// ---------------- launch ----------------------------------------------------
extern "C" void kernel_launch(void* const* d_in, const int* in_sizes, int n_in,
                              void* d_out, int out_size) {
    const float* F   = (const float*)d_in[0];
    const float* Dm  = (const float*)d_in[1];
    const float* Wq  = (const float*)d_in[2];
    const float* Wk  = (const float*)d_in[3];
    const float* Wv  = (const float*)d_in[4];
    const float* gf  = (const float*)d_in[5];
    const float* bf  = (const float*)d_in[6];
    const float* gp  = (const float*)d_in[7];
    const float* bp  = (const float*)d_in[8];
    const float* Wpt = (const float*)d_in[9];
    const float* bpt = (const float*)d_in[10];
    const float* Wph = (const float*)d_in[11];
    float* out = (float*)d_out;

    mgemm_kernel<<<dim3(4, 4), 256>>>(Wq, Wk);
    prep_kernel<<<257, 128>>>(Wv, gp, bp, Wpt, bpt, Wph);
    lnf_kernel<<<ROWS, 256>>>(F, gf, bf);
    bias_t_kernel<<<BIAS_BLOCKS + T_TILES, 256>>>(Dm);
    dim3 g4(NN/64, NN/64, BB);
    s_gemm_kernel<<<g4, 256>>>();
    softmax_out_kernel<<<ROWS, 256>>>(out);
}

// round 6
// speedup vs baseline: 2.5273x; 1.1975x over previous
#include <cuda_runtime.h>

#define BB   4
#define NN   512
#define FD   256
#define AD   256
#define DP   64
#define PD   128
#define ROWS (BB*NN)          /* 2048 */
#define NPAIR (BB*NN*NN)      /* 1048576 */
#define EPSF 1e-3f
#define SCAL 0.0625f          /* 1/sqrt(256) */

#define BIAS_BLOCKS 4096      /* 1048576 rows / 256 rows per block */
#define T_TILES     128       /* (2048/64) * (256/64) */

// ---------------- scratch (device globals; no allocation allowed) ----------
__device__ float d_Fn[ROWS*FD];
__device__ float d_M[FD*FD];         // Wq @ Wk^T
__device__ float d_T[ROWS*FD];       // Fn @ M
__device__ float d_vsum[ROWS];
__device__ float d_gw[DP];
__device__ float d_sgw;
__device__ float d_bconst;
__device__ float d_wvsum[FD];
__device__ float d_bias[NPAIR];
__device__ float d_S[NPAIR];

// ---------------- helpers ---------------------------------------------------
__device__ __forceinline__ float warp_sum(float v) {
    #pragma unroll
    for (int o = 16; o > 0; o >>= 1) v += __shfl_xor_sync(0xffffffffu, v, o);
    return v;
}
__device__ __forceinline__ float warp_max(float v) {
    #pragma unroll
    for (int o = 16; o > 0; o >>= 1) v = fmaxf(v, __shfl_xor_sync(0xffffffffu, v, o));
    return v;
}

// ---------------- K1: prep (grid 257 x 128 threads) -------------------------
__global__ void __launch_bounds__(128)
prep_kernel(const float* __restrict__ Wv,
            const float* __restrict__ gp,
            const float* __restrict__ bp,
            const float* __restrict__ Wpt,
            const float* __restrict__ bpt,
            const float* __restrict__ Wph) {
    int t = threadIdx.x;
    int w = t >> 5, l = t & 31;

    if (blockIdx.x < 256) {
        int f = blockIdx.x;
        __shared__ float s_w[4];
        float2 v = *(const float2*)&Wv[f*AD + t*2];
        float s = warp_sum(v.x + v.y);
        if (l == 0) s_w[w] = s;
        __syncthreads();
        if (t == 0) d_wvsum[f] = s_w[0] + s_w[1] + s_w[2] + s_w[3];
        return;
    }

    __shared__ float red[128];
    int c = t >> 1;              // 0..63
    int j = t & 1;               // half of PD
    float we = 0.f;
    #pragma unroll
    for (int i = 0; i < 16; i++) {
        float4 a = *(const float4*)&Wpt[c*PD + j*64 + i*4];
        float4 b = *(const float4*)&Wph[j*64 + i*4];
        we += a.x*b.x + a.y*b.y + a.z*b.z + a.w*b.w;
    }
    we += __shfl_xor_sync(0xffffffffu, we, 1);
    if (j == 0) d_gw[c] = gp[c] * we;

    float v_sgw = (j == 0) ? gp[c] * we : 0.f;
    float v_bc  = (j == 0) ? bp[c] * we : 0.f;
    float v_bpt = bpt[t] * Wph[t];

    red[t] = v_sgw; __syncthreads();
    #pragma unroll
    for (int o = 64; o > 0; o >>= 1) { if (t < o) red[t] += red[t+o]; __syncthreads(); }
    if (t == 0) d_sgw = red[0];
    __syncthreads();
    red[t] = v_bc + v_bpt; __syncthreads();
    #pragma unroll
    for (int o = 64; o > 0; o >>= 1) { if (t < o) red[t] += red[t+o]; __syncthreads(); }
    if (t == 0) d_bconst = red[0];
}

// ---------------- K0: M = Wq @ Wk^T  (256x256, K=256, NT) -------------------
__global__ void __launch_bounds__(256)
mgemm_kernel(const float* __restrict__ Wq, const float* __restrict__ Wk) {
    __shared__ float As[16][68];
    __shared__ float Bs[16][68];
    int f0 = blockIdx.y * 64;
    int g0 = blockIdx.x * 64;
    int tid = threadIdx.x;
    int lm = tid >> 2;
    int lk = (tid & 3) * 4;
    int ty = tid >> 4, tx = tid & 15;

    float acc[4][4] = {};
    for (int kt = 0; kt < AD; kt += 16) {
        float4 a = *(const float4*)&Wq[(f0 + lm)*AD + kt + lk];
        As[lk+0][lm] = a.x; As[lk+1][lm] = a.y;
        As[lk+2][lm] = a.z; As[lk+3][lm] = a.w;
        float4 c = *(const float4*)&Wk[(g0 + lm)*AD + kt + lk];
        Bs[lk+0][lm] = c.x; Bs[lk+1][lm] = c.y;
        Bs[lk+2][lm] = c.z; Bs[lk+3][lm] = c.w;
        __syncthreads();
        #pragma unroll
        for (int kf = 0; kf < 16; kf++) {
            float4 av = *(const float4*)&As[kf][ty*4];
            float4 bv = *(const float4*)&Bs[kf][tx*4];
            float aa[4] = {av.x, av.y, av.z, av.w};
            float bb[4] = {bv.x, bv.y, bv.z, bv.w};
            #pragma unroll
            for (int i = 0; i < 4; i++)
                #pragma unroll
                for (int j = 0; j < 4; j++)
                    acc[i][j] += aa[i] * bb[j];
        }
        __syncthreads();
    }
    #pragma unroll
    for (int i = 0; i < 4; i++)
        #pragma unroll
        for (int j = 0; j < 4; j++)
            d_M[(f0 + ty*4 + i)*FD + g0 + tx*4 + j] = acc[i][j];
}

// ---------------- K2: LayerNorm(F) -> Fn, vsum ------------------------------
__global__ void __launch_bounds__(256)
lnf_kernel(const float* __restrict__ F,
           const float* __restrict__ gf,
           const float* __restrict__ bf) {
    __shared__ float s_a[8], s_b[8];
    int r = blockIdx.x;
    int t = threadIdx.x;
    int w = t >> 5, l = t & 31;
    float x = F[r*FD + t];

    float sa = warp_sum(x);
    float sb = warp_sum(x*x);
    if (l == 0) { s_a[w] = sa; s_b[w] = sb; }
    __syncthreads();
    float ts = 0.f, tq = 0.f;
    #pragma unroll
    for (int i = 0; i < 8; i++) { ts += s_a[i]; tq += s_b[i]; }
    float mu = ts * (1.f/FD);
    float rstd = rsqrtf(tq * (1.f/FD) - mu*mu + EPSF);
    float fn = (x - mu) * rstd * gf[t] + bf[t];
    d_Fn[r*FD + t] = fn;

    __syncthreads();
    float sv = warp_sum(fn * d_wvsum[t]);
    if (l == 0) s_a[w] = sv;
    __syncthreads();
    if (t == 0) {
        float acc = 0.f;
        #pragma unroll
        for (int i = 0; i < 8; i++) acc += s_a[i];
        d_vsum[r] = acc;
    }
}

// ---------------- K3: fused  T = Fn @ M (first)  ||  bias(D sweep) ----------
// blocks [0, T_TILES)            : T gemm (overlaps with bias sweep)
// blocks [T_TILES, +BIAS_BLOCKS) : D sweep, 8 lanes per 64-float row
__global__ void __launch_bounds__(256, 6)
bias_t_kernel(const float* __restrict__ Dm) {
    int tid = threadIdx.x;

    if (blockIdx.x >= T_TILES) {
        int w = tid >> 5, l = tid & 31;
        int sub = l & 7;          // column group: 2 float4 slots (32B)
        int rr  = l >> 3;         // row within group of 4

        // gw slots for this lane: floats [sub*8, sub*8+8)
        float4 g0 = *(const float4*)&d_gw[sub*8];
        float4 g1 = *(const float4*)&d_gw[sub*8 + 4];
        float sgw = d_sgw, bconst = d_bconst;

        int rowbase = (blockIdx.x - T_TILES) * 256 + w * 32 + rr;
        #pragma unroll
        for (int it = 0; it < 8; it++) {
            int row = rowbase + it * 4;
            const float4* p = (const float4*)&Dm[(size_t)row * DP];
            float4 c0 = __ldcs(p + sub*2);
            float4 c1 = __ldcs(p + sub*2 + 1);

            float s1 = (c0.x+c0.y+c0.z+c0.w) + (c1.x+c1.y+c1.z+c1.w);
            float s2 = c0.x*c0.x+c0.y*c0.y+c0.z*c0.z+c0.w*c0.w
                     + c1.x*c1.x+c1.y*c1.y+c1.z*c1.z+c1.w*c1.w;
            float s3 = c0.x*g0.x+c0.y*g0.y+c0.z*g0.z+c0.w*g0.w
                     + c1.x*g1.x+c1.y*g1.y+c1.z*g1.z+c1.w*g1.w;

            // width-8 xor reduction (3 steps)
            #pragma unroll
            for (int o = 1; o < 8; o <<= 1) {
                s1 += __shfl_xor_sync(0xffffffffu, s1, o);
                s2 += __shfl_xor_sync(0xffffffffu, s2, o);
                s3 += __shfl_xor_sync(0xffffffffu, s3, o);
            }
            if (sub == 0) {
                float mu = s1 * (1.f/DP);
                float var = s2 * (1.f/DP) - mu*mu;
                float rstd = rsqrtf(var + EPSF);
                d_bias[row] = rstd * (s3 - mu*sgw) + bconst;
            }
        }
    } else {
        // ---- T[2048 x 256] = Fn[2048 x 256] @ M[256 x 256] (NN) ----
        __shared__ float As[16][68];
        __shared__ float Bs[16][68];
        int t2 = blockIdx.x;
        int bm = t2 & 31;
        int bn = t2 >> 5;
        int row0 = bm * 64;
        int n0   = bn * 64;

        int lm = tid >> 2;
        int lk = (tid & 3) * 4;
        int bk = tid >> 4;
        int bn4 = (tid & 15) * 4;
        int ty = tid >> 4, tx = tid & 15;

        float acc[4][4] = {};
        for (int kt = 0; kt < FD; kt += 16) {
            float4 a = *(const float4*)&d_Fn[(row0 + lm)*FD + kt + lk];
            As[lk+0][lm] = a.x; As[lk+1][lm] = a.y;
            As[lk+2][lm] = a.z; As[lk+3][lm] = a.w;
            float4 b = *(const float4*)&d_M[(kt + bk)*FD + n0 + bn4];
            Bs[bk][bn4+0] = b.x; Bs[bk][bn4+1] = b.y;
            Bs[bk][bn4+2] = b.z; Bs[bk][bn4+3] = b.w;
            __syncthreads();
            #pragma unroll
            for (int kf = 0; kf < 16; kf++) {
                float4 av = *(const float4*)&As[kf][ty*4];
                float4 bv = *(const float4*)&Bs[kf][tx*4];
                float aa[4] = {av.x, av.y, av.z, av.w};
                float bb[4] = {bv.x, bv.y, bv.z, bv.w};
                #pragma unroll
                for (int i = 0; i < 4; i++)
                    #pragma unroll
                    for (int j = 0; j < 4; j++)
                        acc[i][j] += aa[i] * bb[j];
            }
            __syncthreads();
        }
        #pragma unroll
        for (int i = 0; i < 4; i++) {
            int r = row0 + ty*4 + i;
            #pragma unroll
            for (int j = 0; j < 4; j++)
                d_T[r*FD + n0 + tx*4 + j] = acc[i][j];
        }
    }
}

// ---------------- K4: S = SCAL * (T @ Fn^T + bias) --------------------------
__global__ void __launch_bounds__(256)
s_gemm_kernel() {
    __shared__ float As[16][68];
    __shared__ float Bs[16][68];
    int b  = blockIdx.z;
    int q0 = blockIdx.y * 64;
    int k0 = blockIdx.x * 64;
    const float* A  = d_T  + b*NN*FD;
    const float* Bm = d_Fn + b*NN*FD;

    int tid = threadIdx.x;
    int lm = tid >> 2;
    int lk = (tid & 3) * 4;
    int ty = tid >> 4, tx = tid & 15;

    float acc[4][4] = {};
    for (int kt = 0; kt < FD; kt += 16) {
        float4 a = *(const float4*)&A[(q0 + lm)*FD + kt + lk];
        As[lk+0][lm] = a.x; As[lk+1][lm] = a.y;
        As[lk+2][lm] = a.z; As[lk+3][lm] = a.w;
        float4 c = *(const float4*)&Bm[(k0 + lm)*FD + kt + lk];
        Bs[lk+0][lm] = c.x; Bs[lk+1][lm] = c.y;
        Bs[lk+2][lm] = c.z; Bs[lk+3][lm] = c.w;
        __syncthreads();
        #pragma unroll
        for (int kf = 0; kf < 16; kf++) {
            float4 av = *(const float4*)&As[kf][ty*4];
            float4 bv = *(const float4*)&Bs[kf][tx*4];
            float aa[4] = {av.x, av.y, av.z, av.w};
            float bb[4] = {bv.x, bv.y, bv.z, bv.w};
            #pragma unroll
            for (int i = 0; i < 4; i++)
                #pragma unroll
                for (int j = 0; j < 4; j++)
                    acc[i][j] += aa[i] * bb[j];
        }
        __syncthreads();
    }
    #pragma unroll
    for (int i = 0; i < 4; i++) {
        int q = q0 + ty*4 + i;
        int idx = (b*NN + q)*NN + k0 + tx*4;
        float4 bi = *(const float4*)&d_bias[idx];
        float4 o;
        o.x = SCAL * (acc[i][0] + bi.x);
        o.y = SCAL * (acc[i][1] + bi.y);
        o.z = SCAL * (acc[i][2] + bi.z);
        o.w = SCAL * (acc[i][3] + bi.w);
        *(float4*)&d_S[idx] = o;
    }
}

// ---------------- K5: softmax over k + dot with vsum ------------------------
__global__ void __launch_bounds__(256)
softmax_out_kernel(float* __restrict__ out) {
    __shared__ float s_a[8], s_b[8];
    int r = blockIdx.x;
    int b = r >> 9;
    int t = threadIdx.x;
    int w = t >> 5, l = t & 31;

    float s0 = d_S[r*NN + t];
    float s1 = d_S[r*NN + 256 + t];
    float wm = warp_max(fmaxf(s0, s1));
    if (l == 0) s_a[w] = wm;
    __syncthreads();
    float m = s_a[0];
    #pragma unroll
    for (int i = 1; i < 8; i++) m = fmaxf(m, s_a[i]);

    float e0 = __expf(s0 - m), e1 = __expf(s1 - m);
    float v0 = d_vsum[b*NN + t], v1 = d_vsum[b*NN + 256 + t];
    __syncthreads();
    float se = warp_sum(e0 + e1);
    float sv = warp_sum(e0*v0 + e1*v1);
    if (l == 0) { s_a[w] = se; s_b[w] = sv; }
    __syncthreads();
    if (t == 0) {
        float tse = 0.f, tsv = 0.f;
        #pragma unroll
        for (int i = 0; i < 8; i++) { tse += s_a[i]; tsv += s_b[i]; }
        out[r] = tsv / tse;
    }
}

// ---------------- launch ----------------------------------------------------
extern "C" void kernel_launch(void* const* d_in, const int* in_sizes, int n_in,
                              void* d_out, int out_size) {
    const float* F   = (const float*)d_in[0];
    const float* Dm  = (const float*)d_in[1];
    const float* Wq  = (const float*)d_in[2];
    const float* Wk  = (const float*)d_in[3];
    const float* Wv  = (const float*)d_in[4];
    const float* gf  = (const float*)d_in[5];
    const float* bf  = (const float*)d_in[6];
    const float* gp  = (const float*)d_in[7];
    const float* bp  = (const float*)d_in[8];
    const float* Wpt = (const float*)d_in[9];
    const float* bpt = (const float*)d_in[10];
    const float* Wph = (const float*)d_in[11];
    float* out = (float*)d_out;

    mgemm_kernel<<<dim3(4, 4), 256>>>(Wq, Wk);
    prep_kernel<<<257, 128>>>(Wv, gp, bp, Wpt, bpt, Wph);
    lnf_kernel<<<ROWS, 256>>>(F, gf, bf);
    bias_t_kernel<<<T_TILES + BIAS_BLOCKS, 256>>>(Dm);
    dim3 g4(NN/64, NN/64, BB);
    s_gemm_kernel<<<g4, 256>>>();
    softmax_out_kernel<<<ROWS, 256>>>(out);
}

// round 7
// speedup vs baseline: 2.6318x; 1.0413x over previous
#include <cuda_runtime.h>

#define BB   4
#define NN   512
#define FD   256
#define AD   256
#define DP   64
#define PD   128
#define ROWS (BB*NN)          /* 2048 */
#define NPAIR (BB*NN*NN)      /* 1048576 */
#define EPSF 1e-3f
#define SCAL 0.0625f          /* 1/sqrt(256) */

#define BIAS_BLOCKS 4096      /* 1048576 rows / 256 rows per block */
#define T_TILES     128       /* (2048/64) * (256/64) */

// ---------------- scratch (device globals; no allocation allowed) ----------
__device__ float d_Fn[ROWS*FD];
__device__ float d_M[FD*FD];         // Wq @ Wk^T
__device__ float d_T[ROWS*FD];       // Fn @ M
__device__ float d_vsum[ROWS];
__device__ float d_gw[DP];
__device__ float d_sgw;
__device__ float d_bconst;
__device__ float d_wvsum[FD];
__device__ float d_bias[NPAIR];
__device__ float d_Sa[NPAIR];        // split-K partial (K 0..127)
__device__ float d_Sb[NPAIR];        // split-K partial (K 128..255)

// ---------------- helpers ---------------------------------------------------
__device__ __forceinline__ float warp_sum(float v) {
    #pragma unroll
    for (int o = 16; o > 0; o >>= 1) v += __shfl_xor_sync(0xffffffffu, v, o);
    return v;
}
__device__ __forceinline__ float warp_max(float v) {
    #pragma unroll
    for (int o = 16; o > 0; o >>= 1) v = fmaxf(v, __shfl_xor_sync(0xffffffffu, v, o));
    return v;
}

// ---------------- K1: prep (grid 257 x 128 threads) -------------------------
__global__ void __launch_bounds__(128)
prep_kernel(const float* __restrict__ Wv,
            const float* __restrict__ gp,
            const float* __restrict__ bp,
            const float* __restrict__ Wpt,
            const float* __restrict__ bpt,
            const float* __restrict__ Wph) {
    int t = threadIdx.x;
    int w = t >> 5, l = t & 31;

    if (blockIdx.x < 256) {
        int f = blockIdx.x;
        __shared__ float s_w[4];
        float2 v = *(const float2*)&Wv[f*AD + t*2];
        float s = warp_sum(v.x + v.y);
        if (l == 0) s_w[w] = s;
        __syncthreads();
        if (t == 0) d_wvsum[f] = s_w[0] + s_w[1] + s_w[2] + s_w[3];
        return;
    }

    __shared__ float red[128];
    int c = t >> 1;              // 0..63
    int j = t & 1;               // half of PD
    float we = 0.f;
    #pragma unroll
    for (int i = 0; i < 16; i++) {
        float4 a = *(const float4*)&Wpt[c*PD + j*64 + i*4];
        float4 b = *(const float4*)&Wph[j*64 + i*4];
        we += a.x*b.x + a.y*b.y + a.z*b.z + a.w*b.w;
    }
    we += __shfl_xor_sync(0xffffffffu, we, 1);
    if (j == 0) d_gw[c] = gp[c] * we;

    float v_sgw = (j == 0) ? gp[c] * we : 0.f;
    float v_bc  = (j == 0) ? bp[c] * we : 0.f;
    float v_bpt = bpt[t] * Wph[t];

    red[t] = v_sgw; __syncthreads();
    #pragma unroll
    for (int o = 64; o > 0; o >>= 1) { if (t < o) red[t] += red[t+o]; __syncthreads(); }
    if (t == 0) d_sgw = red[0];
    __syncthreads();
    red[t] = v_bc + v_bpt; __syncthreads();
    #pragma unroll
    for (int o = 64; o > 0; o >>= 1) { if (t < o) red[t] += red[t+o]; __syncthreads(); }
    if (t == 0) d_bconst = red[0];
}

// ---------------- K0: M = Wq @ Wk^T  (256x256, K=256, NT) -------------------
__global__ void __launch_bounds__(256)
mgemm_kernel(const float* __restrict__ Wq, const float* __restrict__ Wk) {
    __shared__ float As[16][68];
    __shared__ float Bs[16][68];
    int f0 = blockIdx.y * 64;
    int g0 = blockIdx.x * 64;
    int tid = threadIdx.x;
    int lm = tid >> 2;
    int lk = (tid & 3) * 4;
    int ty = tid >> 4, tx = tid & 15;

    float acc[4][4] = {};
    for (int kt = 0; kt < AD; kt += 16) {
        float4 a = *(const float4*)&Wq[(f0 + lm)*AD + kt + lk];
        As[lk+0][lm] = a.x; As[lk+1][lm] = a.y;
        As[lk+2][lm] = a.z; As[lk+3][lm] = a.w;
        float4 c = *(const float4*)&Wk[(g0 + lm)*AD + kt + lk];
        Bs[lk+0][lm] = c.x; Bs[lk+1][lm] = c.y;
        Bs[lk+2][lm] = c.z; Bs[lk+3][lm] = c.w;
        __syncthreads();
        #pragma unroll
        for (int kf = 0; kf < 16; kf++) {
            float4 av = *(const float4*)&As[kf][ty*4];
            float4 bv = *(const float4*)&Bs[kf][tx*4];
            float aa[4] = {av.x, av.y, av.z, av.w};
            float bb[4] = {bv.x, bv.y, bv.z, bv.w};
            #pragma unroll
            for (int i = 0; i < 4; i++)
                #pragma unroll
                for (int j = 0; j < 4; j++)
                    acc[i][j] += aa[i] * bb[j];
        }
        __syncthreads();
    }
    #pragma unroll
    for (int i = 0; i < 4; i++)
        #pragma unroll
        for (int j = 0; j < 4; j++)
            d_M[(f0 + ty*4 + i)*FD + g0 + tx*4 + j] = acc[i][j];
}

// ---------------- K2: LayerNorm(F) -> Fn, vsum ------------------------------
__global__ void __launch_bounds__(256)
lnf_kernel(const float* __restrict__ F,
           const float* __restrict__ gf,
           const float* __restrict__ bf) {
    __shared__ float s_a[8], s_b[8];
    int r = blockIdx.x;
    int t = threadIdx.x;
    int w = t >> 5, l = t & 31;
    float x = F[r*FD + t];

    float sa = warp_sum(x);
    float sb = warp_sum(x*x);
    if (l == 0) { s_a[w] = sa; s_b[w] = sb; }
    __syncthreads();
    float ts = 0.f, tq = 0.f;
    #pragma unroll
    for (int i = 0; i < 8; i++) { ts += s_a[i]; tq += s_b[i]; }
    float mu = ts * (1.f/FD);
    float rstd = rsqrtf(tq * (1.f/FD) - mu*mu + EPSF);
    float fn = (x - mu) * rstd * gf[t] + bf[t];
    d_Fn[r*FD + t] = fn;

    __syncthreads();
    float sv = warp_sum(fn * d_wvsum[t]);
    if (l == 0) s_a[w] = sv;
    __syncthreads();
    if (t == 0) {
        float acc = 0.f;
        #pragma unroll
        for (int i = 0; i < 8; i++) acc += s_a[i];
        d_vsum[r] = acc;
    }
}

// ---------------- K3: fused  T = Fn @ M (first)  ||  bias(D sweep) ----------
__global__ void __launch_bounds__(256, 6)
bias_t_kernel(const float* __restrict__ Dm) {
    int tid = threadIdx.x;

    if (blockIdx.x >= T_TILES) {
        int w = tid >> 5, l = tid & 31;
        int sub = l & 7;          // column group: 2 float4 slots (32B)
        int rr  = l >> 3;         // row within group of 4

        float4 g0 = *(const float4*)&d_gw[sub*8];
        float4 g1 = *(const float4*)&d_gw[sub*8 + 4];
        float sgw = d_sgw, bconst = d_bconst;

        int rowbase = (blockIdx.x - T_TILES) * 256 + w * 32 + rr;
        #pragma unroll
        for (int it = 0; it < 8; it++) {
            int row = rowbase + it * 4;
            const float4* p = (const float4*)&Dm[(size_t)row * DP];
            float4 c0 = __ldcs(p + sub*2);
            float4 c1 = __ldcs(p + sub*2 + 1);

            float s1 = (c0.x+c0.y+c0.z+c0.w) + (c1.x+c1.y+c1.z+c1.w);
            float s2 = c0.x*c0.x+c0.y*c0.y+c0.z*c0.z+c0.w*c0.w
                     + c1.x*c1.x+c1.y*c1.y+c1.z*c1.z+c1.w*c1.w;
            float s3 = c0.x*g0.x+c0.y*g0.y+c0.z*g0.z+c0.w*g0.w
                     + c1.x*g1.x+c1.y*g1.y+c1.z*g1.z+c1.w*g1.w;

            #pragma unroll
            for (int o = 1; o < 8; o <<= 1) {
                s1 += __shfl_xor_sync(0xffffffffu, s1, o);
                s2 += __shfl_xor_sync(0xffffffffu, s2, o);
                s3 += __shfl_xor_sync(0xffffffffu, s3, o);
            }
            if (sub == 0) {
                float mu = s1 * (1.f/DP);
                float var = s2 * (1.f/DP) - mu*mu;
                float rstd = rsqrtf(var + EPSF);
                d_bias[row] = rstd * (s3 - mu*sgw) + bconst;
            }
        }
    } else {
        // ---- T[2048 x 256] = Fn[2048 x 256] @ M[256 x 256] (NN) ----
        __shared__ float As[16][68];
        __shared__ float Bs[16][68];
        int t2 = blockIdx.x;
        int bm = t2 & 31;
        int bn = t2 >> 5;
        int row0 = bm * 64;
        int n0   = bn * 64;

        int lm = tid >> 2;
        int lk = (tid & 3) * 4;
        int bk = tid >> 4;
        int bn4 = (tid & 15) * 4;
        int ty = tid >> 4, tx = tid & 15;

        float acc[4][4] = {};
        for (int kt = 0; kt < FD; kt += 16) {
            float4 a = *(const float4*)&d_Fn[(row0 + lm)*FD + kt + lk];
            As[lk+0][lm] = a.x; As[lk+1][lm] = a.y;
            As[lk+2][lm] = a.z; As[lk+3][lm] = a.w;
            float4 b = *(const float4*)&d_M[(kt + bk)*FD + n0 + bn4];
            Bs[bk][bn4+0] = b.x; Bs[bk][bn4+1] = b.y;
            Bs[bk][bn4+2] = b.z; Bs[bk][bn4+3] = b.w;
            __syncthreads();
            #pragma unroll
            for (int kf = 0; kf < 16; kf++) {
                float4 av = *(const float4*)&As[kf][ty*4];
                float4 bv = *(const float4*)&Bs[kf][tx*4];
                float aa[4] = {av.x, av.y, av.z, av.w};
                float bb[4] = {bv.x, bv.y, bv.z, bv.w};
                #pragma unroll
                for (int i = 0; i < 4; i++)
                    #pragma unroll
                    for (int j = 0; j < 4; j++)
                        acc[i][j] += aa[i] * bb[j];
            }
            __syncthreads();
        }
        #pragma unroll
        for (int i = 0; i < 4; i++) {
            int r = row0 + ty*4 + i;
            #pragma unroll
            for (int j = 0; j < 4; j++)
                d_T[r*FD + n0 + tx*4 + j] = acc[i][j];
        }
    }
}

// ---------------- K4: split-K partial GEMM  Sa/Sb = T @ Fn^T ----------------
// grid (8, 8, 8): z = b*2 + half; each block does K-range [half*128, +128)
// with global->register prefetch double buffering.
__global__ void __launch_bounds__(256)
s_gemm_kernel() {
    __shared__ float As[16][68];
    __shared__ float Bs[16][68];
    int z  = blockIdx.z;
    int b  = z >> 1;
    int half = z & 1;
    int q0 = blockIdx.y * 64;
    int k0 = blockIdx.x * 64;
    const float* A  = d_T  + b*NN*FD;
    const float* Bm = d_Fn + b*NN*FD;
    float* Sp = half ? d_Sb : d_Sa;

    int tid = threadIdx.x;
    int lm = tid >> 2;
    int lk = (tid & 3) * 4;
    int ty = tid >> 4, tx = tid & 15;

    int kbase = half * 128;
    float4 pa = *(const float4*)&A [(q0 + lm)*FD + kbase + lk];
    float4 pb = *(const float4*)&Bm[(k0 + lm)*FD + kbase + lk];

    float acc[4][4] = {};
    #pragma unroll
    for (int c = 0; c < 8; c++) {
        As[lk+0][lm] = pa.x; As[lk+1][lm] = pa.y;
        As[lk+2][lm] = pa.z; As[lk+3][lm] = pa.w;
        Bs[lk+0][lm] = pb.x; Bs[lk+1][lm] = pb.y;
        Bs[lk+2][lm] = pb.z; Bs[lk+3][lm] = pb.w;
        __syncthreads();
        if (c < 7) {
            int kt = kbase + (c+1)*16;
            pa = *(const float4*)&A [(q0 + lm)*FD + kt + lk];
            pb = *(const float4*)&Bm[(k0 + lm)*FD + kt + lk];
        }
        #pragma unroll
        for (int kf = 0; kf < 16; kf++) {
            float4 av = *(const float4*)&As[kf][ty*4];
            float4 bv = *(const float4*)&Bs[kf][tx*4];
            float aa[4] = {av.x, av.y, av.z, av.w};
            float bb[4] = {bv.x, bv.y, bv.z, bv.w};
            #pragma unroll
            for (int i = 0; i < 4; i++)
                #pragma unroll
                for (int j = 0; j < 4; j++)
                    acc[i][j] += aa[i] * bb[j];
        }
        __syncthreads();
    }
    #pragma unroll
    for (int i = 0; i < 4; i++) {
        int q = q0 + ty*4 + i;
        int idx = (b*NN + q)*NN + k0 + tx*4;
        float4 o;
        o.x = acc[i][0]; o.y = acc[i][1]; o.z = acc[i][2]; o.w = acc[i][3];
        *(float4*)&Sp[idx] = o;
    }
}

// ---------------- K5: combine + softmax + dot with vsum ---------------------
__global__ void __launch_bounds__(256)
softmax_out_kernel(float* __restrict__ out) {
    __shared__ float s_a[8], s_b[8];
    int r = blockIdx.x;
    int b = r >> 9;
    int t = threadIdx.x;
    int w = t >> 5, l = t & 31;

    int i0 = r*NN + t, i1 = r*NN + 256 + t;
    float s0 = SCAL * (d_Sa[i0] + d_Sb[i0] + d_bias[i0]);
    float s1 = SCAL * (d_Sa[i1] + d_Sb[i1] + d_bias[i1]);
    float wm = warp_max(fmaxf(s0, s1));
    if (l == 0) s_a[w] = wm;
    __syncthreads();
    float m = s_a[0];
    #pragma unroll
    for (int i = 1; i < 8; i++) m = fmaxf(m, s_a[i]);

    float e0 = __expf(s0 - m), e1 = __expf(s1 - m);
    float v0 = d_vsum[b*NN + t], v1 = d_vsum[b*NN + 256 + t];
    __syncthreads();
    float se = warp_sum(e0 + e1);
    float sv = warp_sum(e0*v0 + e1*v1);
    if (l == 0) { s_a[w] = se; s_b[w] = sv; }
    __syncthreads();
    if (t == 0) {
        float tse = 0.f, tsv = 0.f;
        #pragma unroll
        for (int i = 0; i < 8; i++) { tse += s_a[i]; tsv += s_b[i]; }
        out[r] = tsv / tse;
    }
}

// ---------------- launch ----------------------------------------------------
extern "C" void kernel_launch(void* const* d_in, const int* in_sizes, int n_in,
                              void* d_out, int out_size) {
    const float* F   = (const float*)d_in[0];
    const float* Dm  = (const float*)d_in[1];
    const float* Wq  = (const float*)d_in[2];
    const float* Wk  = (const float*)d_in[3];
    const float* Wv  = (const float*)d_in[4];
    const float* gf  = (const float*)d_in[5];
    const float* bf  = (const float*)d_in[6];
    const float* gp  = (const float*)d_in[7];
    const float* bp  = (const float*)d_in[8];
    const float* Wpt = (const float*)d_in[9];
    const float* bpt = (const float*)d_in[10];
    const float* Wph = (const float*)d_in[11];
    float* out = (float*)d_out;

    mgemm_kernel<<<dim3(4, 4), 256>>>(Wq, Wk);
    prep_kernel<<<257, 128>>>(Wv, gp, bp, Wpt, bpt, Wph);
    lnf_kernel<<<ROWS, 256>>>(F, gf, bf);
    bias_t_kernel<<<T_TILES + BIAS_BLOCKS, 256>>>(Dm);
    dim3 g4(NN/64, NN/64, BB*2);
    s_gemm_kernel<<<g4, 256>>>();
    softmax_out_kernel<<<ROWS, 256>>>(out);
}